// round 16
// baseline (speedup 1.0000x reference)
#include <cuda_runtime.h>
#include <cuda_fp16.h>
#include <cstdint>
#include <math.h>

#define N_TOT   131072
#define D       512
#define DA      256
#define NH      4
#define NC      53
#define BAG     16
#define NBAGS   8192

#define MT      64          // CTA rows (4 bags)
#define KCH     32          // K chunk (64 bytes fp16) -- triple buffered
#define NCHUNK  (D / KCH)   // 16
#define NTILES  (N_TOT / MT)  // 2048
#define GRID    304         // 2 CTAs x 152 SMs, persistent

// ---------------------------------------------------------------------------
// device scratch (allocation is forbidden)
// ---------------------------------------------------------------------------
__device__ float g_WcT[NC * D];
__device__ float g_rep[NBAGS * D];                 // bag representations
__device__ __align__(256) __half g_W1hH[DA * D];   // W1^T fp16, (n, k) k-contig

// ---------------------------------------------------------------------------
// helpers
// ---------------------------------------------------------------------------
__device__ __forceinline__ uint32_t smem_u32(const void* p) {
    uint32_t a;
    asm("{ .reg .u64 t; cvta.to.shared.u64 t, %1; cvt.u32.u64 %0, t; }" : "=r"(a) : "l"(p));
    return a;
}
__device__ __forceinline__ uint32_t sw128(uint32_t o) { return o ^ ((o >> 3) & 0x70); }
__device__ __forceinline__ uint32_t sw64 (uint32_t o) { return o ^ ((o >> 3) & 0x30); }

#define CP_ASYNC16(dst, src) \
    asm volatile("cp.async.cg.shared.global [%0], [%1], 16;" :: "r"(dst), "l"(src) : "memory")
#define CP_COMMIT() asm volatile("cp.async.commit_group;" ::: "memory")
#define CP_WAIT1()  asm volatile("cp.async.wait_group 1;" ::: "memory")
#define CP_WAIT0()  asm volatile("cp.async.wait_group 0;" ::: "memory")
#define PREFETCH_L2(p) asm volatile("prefetch.global.L2 [%0];" :: "l"(p))

__device__ __forceinline__ void ldsm_x4(uint32_t& r0, uint32_t& r1, uint32_t& r2,
                                        uint32_t& r3, uint32_t addr) {
    asm volatile("ldmatrix.sync.aligned.m8n8.x4.shared.b16 {%0,%1,%2,%3}, [%4];"
                 : "=r"(r0), "=r"(r1), "=r"(r2), "=r"(r3) : "r"(addr));
}
__device__ __forceinline__ void mma_f16(float* d, const uint32_t* a, const uint32_t* b) {
    asm volatile("mma.sync.aligned.m16n8k16.row.col.f32.f16.f16.f32 "
                 "{%0,%1,%2,%3}, {%4,%5,%6,%7}, {%8,%9}, {%0,%1,%2,%3};"
                 : "+f"(d[0]), "+f"(d[1]), "+f"(d[2]), "+f"(d[3])
                 : "r"(a[0]), "r"(a[1]), "r"(a[2]), "r"(a[3]), "r"(b[0]), "r"(b[1]));
}
__device__ __forceinline__ float ftanh(float v) {
    float t;
    asm("tanh.approx.f32 %0, %1;" : "=f"(t) : "f"(v));
    return t;
}
__device__ __forceinline__ uint32_t pack_h2(float a, float b) {
    __half2 h = __floats2half2_rn(a, b);
    return *reinterpret_cast<uint32_t*>(&h);
}

// ---------------------------------------------------------------------------
// prep kernel (merged): W1 -> fp16 transpose; Wc -> transpose
// ---------------------------------------------------------------------------
__global__ void prep_kernel(const float* __restrict__ W1,
                            const float* __restrict__ Wc) {
    int b = blockIdx.x;
    if (b < 512) {
        int i = b * 256 + threadIdx.x;
        int k = i >> 8, n = i & 255;
        g_W1hH[n * D + k] = __float2half_rn(W1[i]);
    } else {
        int i = (b - 512) * 256 + threadIdx.x;
        if (i < D * NC) {
            int d = i / NC, c = i - d * NC;
            g_WcT[c * D + d] = Wc[i];
        }
    }
}

// ---------------------------------------------------------------------------
// persistent fused kernel: per tile (64 rows): fp16 GEMM (64x256x512)
//   + tanh/W2 + bag softmax + bag weighted-sum -> g_rep
// smem: A 64K @0 | B 3x16K @65536. Epilogue scratch aliases B stage 2
// (sRed4 @98304, sw @102400) — stage 2 is dead after chunk 14.
// ---------------------------------------------------------------------------
#define SOF_A    0
#define SOF_B    65536
#define BSTG     16384
#define SO_RED   98304
#define SO_SW    102400
#define SMEM_SZ  (SOF_B + 3 * BSTG)   // 114688

__global__ void __launch_bounds__(256, 2) fused_kernel(
    const float* __restrict__ x,
    const float* __restrict__ W2)
{
    extern __shared__ char smem[];
    const uint32_t sb = smem_u32(smem);
    const int tid  = threadIdx.x;
    const int warp = tid >> 5;
    const int lane = tid & 31;
    const int wm = warp & 1;        // 0..1 : 32-row group
    const int wn = warp >> 1;       // 0..3 : 64-col group

    // ---- precomputed swizzled LDSM base offsets (tile-invariant) ----
    uint32_t preA[2];
#pragma unroll
    for (int mt = 0; mt < 2; mt++) {
        int row = wm * 32 + mt * 16 + ((lane >> 3) & 1) * 8 + (lane & 7);
        int kh  = (lane >> 4) * 8;
        preA[mt] = sw128((uint32_t)(row * 128 + kh * 2));
    }
    uint32_t preB[4];
#pragma unroll
    for (int np = 0; np < 4; np++) {
        int nrow = wn * 64 + np * 16 + (lane >> 4) * 8 + (lane & 7);
        int kh   = ((lane >> 3) & 1) * 8;
        preB[np] = sw64((uint32_t)(nrow * 64 + kh * 2));
    }
    // B cp.async source/dst (tile-invariant): thread covers 4 x 16B per chunk
    uint32_t bdst[4]; const __half* bsrc[4];
#pragma unroll
    for (int i = 0; i < 4; i++) {
        int f = tid + i * 256;
        int n = f >> 2, k8 = f & 3;
        bdst[i] = sw64((uint32_t)(n * 64 + k8 * 16));
        bsrc[i] = g_W1hH + n * D + k8 * 8;
    }

    // ---- bootstrap: B chunks 0,1 of first tile ----
#pragma unroll
    for (int i = 0; i < 4; i++) CP_ASYNC16(sb + SOF_B + bdst[i], bsrc[i]);
    CP_COMMIT();
#pragma unroll
    for (int i = 0; i < 4; i++) CP_ASYNC16(sb + SOF_B + BSTG + bdst[i], bsrc[i] + KCH);
    CP_COMMIT();

    const int gid = lane >> 2, tig = lane & 3;
    float* sRed4 = (float*)(smem + SO_RED);
    float* sw    = (float*)(smem + SO_SW);
    const float4* W2v = (const float4*)W2;

    for (int t = blockIdx.x; t < NTILES; t += GRID) {
        const float* xrow = x + (size_t)t * MT * D;

        // ---- A tile: ldg fp32 -> fp16 -> STS (8 sub-tiles, sw128) ----
#pragma unroll
        for (int i = 0; i < 32; i++) {
            int f  = tid + i * 256;
            int r  = f >> 7;
            int k4 = (f & 127) << 2;
            float4 v = *(const float4*)&xrow[(size_t)r * D + k4];
            int chunk = k4 >> 6;
            int inner = (k4 & 63) << 1;
            *(uint2*)(smem + SOF_A + chunk * 8192 + sw128((uint32_t)(r * 128 + inner))) =
                make_uint2(pack_h2(v.x, v.y), pack_h2(v.z, v.w));
        }
        // ---- warm L2 with next tile's x (overlaps this tile's GEMM) ----
        if (t + GRID < NTILES) {
            const float* nx = x + (size_t)(t + GRID) * MT * D;
#pragma unroll
            for (int i = 0; i < 4; i++) PREFETCH_L2(nx + (size_t)(tid + i * 256) * 32);
        }

        float acc[2][8][4];
#pragma unroll
        for (int mt = 0; mt < 2; mt++)
#pragma unroll
            for (int nt = 0; nt < 8; nt++)
#pragma unroll
                for (int q = 0; q < 4; q++) acc[mt][nt][q] = 0.0f;

        // ---- main loop: 16 chunks, 3-stage B ring, prefetch distance 2 ----
#pragma unroll
        for (int c = 0; c < NCHUNK; c++) {
            if (c == NCHUNK - 1) CP_WAIT0(); else CP_WAIT1();
            __syncthreads();
            if (c + 2 < NCHUNK) {
#pragma unroll
                for (int i = 0; i < 4; i++)
                    CP_ASYNC16(sb + SOF_B + ((c + 2) % 3) * BSTG + bdst[i],
                               bsrc[i] + (c + 2) * KCH);
                CP_COMMIT();
            }

            const uint32_t stgA = sb + SOF_A + (c >> 1) * 8192;
            const uint32_t abyte = (uint32_t)((c & 1) * 64);
            const uint32_t stgB = sb + SOF_B + (c % 3) * BSTG;

            uint32_t ah[2][2][4];
#pragma unroll
            for (int ks = 0; ks < 2; ks++)
#pragma unroll
                for (int mt = 0; mt < 2; mt++)
                    ldsm_x4(ah[ks][mt][0], ah[ks][mt][1], ah[ks][mt][2], ah[ks][mt][3],
                            stgA + (preA[mt] ^ (abyte + (uint32_t)(ks * 32))));

#pragma unroll
            for (int ks = 0; ks < 2; ks++) {
                const uint32_t kbB = (uint32_t)(ks * 32);
                uint32_t bh[8][2];
#pragma unroll
                for (int np = 0; np < 4; np++)
                    ldsm_x4(bh[2*np][0], bh[2*np][1], bh[2*np+1][0], bh[2*np+1][1],
                            stgB + (preB[np] ^ kbB));
#pragma unroll
                for (int mt = 0; mt < 2; mt++)
#pragma unroll
                    for (int nt = 0; nt < 8; nt++)
                        mma_f16(acc[mt][nt], ah[ks][mt], bh[nt]);
            }
        }

        __syncthreads();   // all warps done with all B stages + A chunks

        // ---- issue next tile's B(0),B(1) now; they land during the epilogue ----
        if (t + GRID < NTILES) {
#pragma unroll
            for (int i = 0; i < 4; i++) CP_ASYNC16(sb + SOF_B + bdst[i], bsrc[i]);
            CP_COMMIT();
#pragma unroll
            for (int i = 0; i < 4; i++) CP_ASYNC16(sb + SOF_B + BSTG + bdst[i], bsrc[i] + KCH);
            CP_COMMIT();
        }

        // ---- epilogue 1: tanh -> x W2 partials (W2 via L1-resident __ldg) ----
#pragma unroll
        for (int mt = 0; mt < 2; mt++) {
            float p0[4] = {0, 0, 0, 0}, p1[4] = {0, 0, 0, 0};
#pragma unroll
            for (int nt = 0; nt < 8; nt++) {
                int col = wn * 64 + nt * 8 + tig * 2;
                float4 wa = __ldg(&W2v[col]);
                float4 wb = __ldg(&W2v[col + 1]);
                float t0 = ftanh(acc[mt][nt][0]);
                float t1 = ftanh(acc[mt][nt][1]);
                float t2 = ftanh(acc[mt][nt][2]);
                float t3 = ftanh(acc[mt][nt][3]);
                p0[0] = fmaf(t0, wa.x, fmaf(t1, wb.x, p0[0]));
                p0[1] = fmaf(t0, wa.y, fmaf(t1, wb.y, p0[1]));
                p0[2] = fmaf(t0, wa.z, fmaf(t1, wb.z, p0[2]));
                p0[3] = fmaf(t0, wa.w, fmaf(t1, wb.w, p0[3]));
                p1[0] = fmaf(t2, wa.x, fmaf(t3, wb.x, p1[0]));
                p1[1] = fmaf(t2, wa.y, fmaf(t3, wb.y, p1[1]));
                p1[2] = fmaf(t2, wa.z, fmaf(t3, wb.z, p1[2]));
                p1[3] = fmaf(t2, wa.w, fmaf(t3, wb.w, p1[3]));
            }
#pragma unroll
            for (int h = 0; h < 4; h++) {
                p0[h] += __shfl_xor_sync(0xffffffffu, p0[h], 1);
                p0[h] += __shfl_xor_sync(0xffffffffu, p0[h], 2);
                p1[h] += __shfl_xor_sync(0xffffffffu, p1[h], 1);
                p1[h] += __shfl_xor_sync(0xffffffffu, p1[h], 2);
            }
            if (tig == 0) {
                int r0 = wm * 32 + mt * 16 + gid;
                int r1 = r0 + 8;
#pragma unroll
                for (int h = 0; h < 4; h++) {
                    sRed4[(wn * 64 + r0) * 4 + h] = p0[h];
                    sRed4[(wn * 64 + r1) * 4 + h] = p1[h];
                }
            }
        }
        __syncthreads();

        // ---- epilogue 2: per-bag softmax (16-lane groups), head-mean ----
        if (tid < MT) {
            float sc[4];
#pragma unroll
            for (int h = 0; h < 4; h++)
                sc[h] = sRed4[(0 * 64 + tid) * 4 + h] + sRed4[(1 * 64 + tid) * 4 + h]
                      + sRed4[(2 * 64 + tid) * 4 + h] + sRed4[(3 * 64 + tid) * 4 + h];
            float wsum = 0.f;
#pragma unroll
            for (int h = 0; h < 4; h++) {
                float mx = sc[h];
#pragma unroll
                for (int o = 1; o < 16; o <<= 1)
                    mx = fmaxf(mx, __shfl_xor_sync(0xffffffffu, mx, o));
                float e = __expf(sc[h] - mx);
                float den = e;
#pragma unroll
                for (int o = 1; o < 16; o <<= 1)
                    den += __shfl_xor_sync(0xffffffffu, den, o);
                wsum += e / den;
            }
            sw[tid] = 0.25f * wsum;
        }
        __syncthreads();

        // ---- epilogue 3: bag weighted sums from resident fp16 A -> g_rep ----
        {
            const int bag = tid >> 6;
            const int cg  = tid & 63;
            const int chunk = cg >> 3;
            const int innerb = (cg & 7) * 16;
            const uint32_t abase = sb + SOF_A + chunk * 8192;

            float a8[8];
#pragma unroll
            for (int j = 0; j < 8; j++) a8[j] = 0.f;
#pragma unroll
            for (int r = 0; r < BAG; r++) {
                int row = bag * BAG + r;
                float w = sw[row];
                uint4 v;
                asm volatile("ld.shared.v4.u32 {%0,%1,%2,%3}, [%4];"
                             : "=r"(v.x), "=r"(v.y), "=r"(v.z), "=r"(v.w)
                             : "r"(abase + sw128((uint32_t)(row * 128 + innerb))));
                const __half2* h2 = (const __half2*)&v;
#pragma unroll
                for (int q = 0; q < 4; q++) {
                    float2 f2 = __half22float2(h2[q]);
                    a8[2*q]   = fmaf(w, f2.x, a8[2*q]);
                    a8[2*q+1] = fmaf(w, f2.y, a8[2*q+1]);
                }
            }
            float* dst = g_rep + ((size_t)t * 4 + bag) * D + cg * 8;
            *(float4*)(dst)     = make_float4(a8[0], a8[1], a8[2], a8[3]);
            *(float4*)(dst + 4) = make_float4(a8[4], a8[5], a8[6], a8[7]);
        }
        __syncthreads();   // A region free for next tile's STS
    }
}

// ---------------------------------------------------------------------------
// classifier kernel: out[b, c] = g_rep[b] . g_WcT[c] + bc[c]
// ---------------------------------------------------------------------------
#define CLS_BAGS 8
__global__ __launch_bounds__(256) void cls_kernel(
    const float* __restrict__ bc,
    float* __restrict__ out)
{
    __shared__ float rep_s[CLS_BAGS * D];   // 16 KB
    const int tid = threadIdx.x;
    const size_t bagBase = (size_t)blockIdx.x * CLS_BAGS;

    const float4* gr = (const float4*)(g_rep + bagBase * D);
    float4* rs = (float4*)rep_s;
#pragma unroll
    for (int i = 0; i < 4; i++) rs[tid + i * 256] = gr[tid + i * 256];
    __syncthreads();

    const int warp = tid >> 5, lane = tid & 31;
    for (int c = warp; c < NC; c += 8) {
        const float4* wc = (const float4*)&g_WcT[c * D];
        float4 w0 = wc[lane], w1 = wc[lane + 32], w2 = wc[lane + 64], w3 = wc[lane + 96];
        float bcv = bc[c];
#pragma unroll
        for (int b = 0; b < CLS_BAGS; b++) {
            const float4* rp = (const float4*)&rep_s[b * D];
            float4 r0 = rp[lane], r1 = rp[lane + 32], r2 = rp[lane + 64], r3 = rp[lane + 96];
            float s = 0.f;
            s = fmaf(r0.x, w0.x, s); s = fmaf(r0.y, w0.y, s);
            s = fmaf(r0.z, w0.z, s); s = fmaf(r0.w, w0.w, s);
            s = fmaf(r1.x, w1.x, s); s = fmaf(r1.y, w1.y, s);
            s = fmaf(r1.z, w1.z, s); s = fmaf(r1.w, w1.w, s);
            s = fmaf(r2.x, w2.x, s); s = fmaf(r2.y, w2.y, s);
            s = fmaf(r2.z, w2.z, s); s = fmaf(r2.w, w2.w, s);
            s = fmaf(r3.x, w3.x, s); s = fmaf(r3.y, w3.y, s);
            s = fmaf(r3.z, w3.z, s); s = fmaf(r3.w, w3.w, s);
            s += __shfl_xor_sync(0xffffffffu, s, 16);
            s += __shfl_xor_sync(0xffffffffu, s, 8);
            s += __shfl_xor_sync(0xffffffffu, s, 4);
            s += __shfl_xor_sync(0xffffffffu, s, 2);
            s += __shfl_xor_sync(0xffffffffu, s, 1);
            if (lane == 0) out[(bagBase + b) * NC + c] = s + bcv;
        }
    }
}

// ---------------------------------------------------------------------------
extern "C" void kernel_launch(void* const* d_in, const int* in_sizes, int n_in,
                              void* d_out, int out_size)
{
    const float* x  = (const float*)d_in[0];
    const float* W1 = (const float*)d_in[1];
    const float* W2 = (const float*)d_in[2];
    const float* Wc = (const float*)d_in[3];
    const float* bc = (const float*)d_in[4];
    float* out = (float*)d_out;

    cudaFuncSetAttribute(fused_kernel,
                         cudaFuncAttributeMaxDynamicSharedMemorySize, SMEM_SZ);

    prep_kernel<<<512 + (D * NC + 255) / 256, 256>>>(W1, Wc);
    fused_kernel<<<GRID, 256, SMEM_SZ>>>(x, W2);
    cls_kernel<<<NBAGS / CLS_BAGS, 256>>>(bc, out);
}